// round 1
// baseline (speedup 1.0000x reference)
#include <cuda_runtime.h>
#include <math.h>

#define NN 100000
#define EE 1600000

// Scratch (device globals; no allocation allowed)
__device__ float  g_xw[(size_t)NN * 64];    // x@W1[:64] + b1
__device__ float  g_seg[(size_t)NN * 64];   // segment-max result
__device__ float4 g_ppf[EE];                // CSR-ordered ppf features
__device__ int    g_col[EE];                // CSR-ordered target nodes
__device__ int    g_deg[NN];
__device__ int    g_off[NN + 1];
__device__ int    g_cur[NN];
__device__ double g_sum;
__device__ float  g_invmean;

// ---------------------------------------------------------------- zero
__global__ void k_zero(int n) {
    int i = blockIdx.x * 256 + threadIdx.x;
    if (i < n) g_deg[i] = 0;
    if (i == 0) g_sum = 0.0;
}

// ---------------------------------------------------------------- xw = x @ W1[:64,:] + b1
// 64 nodes x 64 cols per block, 256 threads, 4x4 register tile per thread.
__global__ void k_xw(const float* __restrict__ x, const float* __restrict__ W1,
                     const float* __restrict__ b1, int n) {
    __shared__ float xs[64][65];
    __shared__ float ws[64][64];
    int n0 = blockIdx.x * 64;
    for (int i = threadIdx.x; i < 4096; i += 256) ws[i >> 6][i & 63] = W1[i];
    for (int i = threadIdx.x; i < 4096; i += 256) {
        int r = i >> 6, c = i & 63;
        xs[r][c] = (n0 + r < n) ? x[(size_t)(n0 + r) * 64 + c] : 0.f;
    }
    __syncthreads();
    int tx = threadIdx.x & 15, ty = threadIdx.x >> 4;
    float acc[4][4];
#pragma unroll
    for (int j = 0; j < 4; j++) {
        float b = b1[tx * 4 + j];
#pragma unroll
        for (int i = 0; i < 4; i++) acc[i][j] = b;
    }
#pragma unroll 16
    for (int d = 0; d < 64; d++) {
        float a[4];
#pragma unroll
        for (int i = 0; i < 4; i++) a[i] = xs[ty * 4 + i][d];
        float4 w = *(const float4*)&ws[d][tx * 4];
#pragma unroll
        for (int i = 0; i < 4; i++) {
            acc[i][0] = fmaf(a[i], w.x, acc[i][0]);
            acc[i][1] = fmaf(a[i], w.y, acc[i][1]);
            acc[i][2] = fmaf(a[i], w.z, acc[i][2]);
            acc[i][3] = fmaf(a[i], w.w, acc[i][3]);
        }
    }
#pragma unroll
    for (int i = 0; i < 4; i++) {
        int node = n0 + ty * 4 + i;
        if (node < n) {
            float4 v = make_float4(acc[i][0], acc[i][1], acc[i][2], acc[i][3]);
            *(float4*)&g_xw[(size_t)node * 64 + tx * 4] = v;
        }
    }
}

// ---------------------------------------------------------------- per-edge: degree counts + sq-dist sum
__global__ void k_prep(const int* __restrict__ ei, const float* __restrict__ pos, int E) {
    int e = blockIdx.x * 256 + threadIdx.x;
    float dist = 0.f;
    if (e < E) {
        int r = ei[e], c = ei[E + e];
        float dx = pos[c * 3 + 0] - pos[r * 3 + 0];
        float dy = pos[c * 3 + 1] - pos[r * 3 + 1];
        float dz = pos[c * 3 + 2] - pos[r * 3 + 2];
        dist = dx * dx + dy * dy + dz * dz;
        atomicAdd(&g_deg[r], 1);
    }
#pragma unroll
    for (int o = 16; o > 0; o >>= 1) dist += __shfl_down_sync(0xffffffffu, dist, o);
    if ((threadIdx.x & 31) == 0) atomicAdd(&g_sum, (double)dist);
}

// ---------------------------------------------------------------- exclusive scan of degrees (single block)
__global__ void k_scan(int n, int E) {
    const int T = 1024;
    int t = threadIdx.x;
    int chunk = (n + T - 1) / T;
    int beg = t * chunk;
    int end = beg + chunk; if (end > n) end = n;
    int s = 0;
    for (int i = beg; i < end && i < n; i++) s += g_deg[i];

    int lane = t & 31, wid = t >> 5;
    int v = s;
#pragma unroll
    for (int o = 1; o < 32; o <<= 1) {
        int y = __shfl_up_sync(0xffffffffu, v, o);
        if (lane >= o) v += y;
    }
    __shared__ int wsum[32];
    if (lane == 31) wsum[wid] = v;
    __syncthreads();
    if (wid == 0) {
        int u = wsum[lane];
#pragma unroll
        for (int o = 1; o < 32; o <<= 1) {
            int y = __shfl_up_sync(0xffffffffu, u, o);
            if (lane >= o) u += y;
        }
        wsum[lane] = u;
    }
    __syncthreads();
    int excl = v - s + (wid ? wsum[wid - 1] : 0);

    int run = excl;
    for (int i = beg; i < end && i < n; i++) {
        int d = g_deg[i];
        g_off[i] = run;
        g_cur[i] = run;
        run += d;
    }
    if (t == 0) {
        g_off[n] = wsum[31];
        // inv mean of squared distances over E + n entries (self-loops add 0)
        g_invmean = (float)((double)(E + n) / g_sum);
    }
}

// ---------------------------------------------------------------- ppf + scatter into CSR
__device__ __forceinline__ float ppf_angle(float ax, float ay, float az,
                                           float bx, float by, float bz) {
    float cx = ay * bz - az * by;
    float cy = az * bx - ax * bz;
    float cz = ax * by - ay * bx;
    float dot = ax * bx + ay * by + az * bz;
    return atan2f(sqrtf(cx * cx + cy * cy + cz * cz), dot);
}

__global__ void k_scatter(const int* __restrict__ ei, const float* __restrict__ pos,
                          const float* __restrict__ nrm, int E) {
    int e = blockIdx.x * 256 + threadIdx.x;
    if (e >= E) return;
    int r = ei[e], c = ei[E + e];
    float dx = pos[c * 3 + 0] - pos[r * 3 + 0];
    float dy = pos[c * 3 + 1] - pos[r * 3 + 1];
    float dz = pos[c * 3 + 2] - pos[r * 3 + 2];
    float n1x = nrm[r * 3 + 0], n1y = nrm[r * 3 + 1], n1z = nrm[r * 3 + 2];
    float n2x = nrm[c * 3 + 0], n2y = nrm[c * 3 + 1], n2z = nrm[c * 3 + 2];
    float dist = (dx * dx + dy * dy + dz * dz) * g_invmean;
    float a1 = ppf_angle(n1x, n1y, n1z, dx, dy, dz);
    float a2 = ppf_angle(n2x, n2y, n2z, dx, dy, dz);
    float a3 = ppf_angle(n1x, n1y, n1z, n2x, n2y, n2z);
    int p = atomicAdd(&g_cur[r], 1);
    g_col[p] = c;
    g_ppf[p] = make_float4(dist, a1, a2, a3);
}

// ---------------------------------------------------------------- warp-per-node max reduction
// lane owns dims [2*lane, 2*lane+1]; acc init = relu(xw[node]) handles the self-loop.
__global__ void k_node(const float* __restrict__ W1, int n) {
    int warp = (blockIdx.x * 256 + threadIdx.x) >> 5;
    int lane = threadIdx.x & 31;
    if (warp >= n) return;
    int node = warp;

    const float* Wp = W1 + 64 * 64;
    float2 w0 = *(const float2*)&Wp[0 * 64 + lane * 2];
    float2 w1 = *(const float2*)&Wp[1 * 64 + lane * 2];
    float2 w2 = *(const float2*)&Wp[2 * 64 + lane * 2];
    float2 w3 = *(const float2*)&Wp[3 * 64 + lane * 2];

    float2 xw = *(const float2*)&g_xw[(size_t)node * 64 + lane * 2];
    float ax = fmaxf(xw.x, 0.f);
    float ay = fmaxf(xw.y, 0.f);

    int beg = g_off[node];
    int end = g_off[node + 1];
    for (int i = beg; i < end; i++) {
        int c = g_col[i];
        float4 p = g_ppf[i];
        float2 xc = *(const float2*)&g_xw[(size_t)c * 64 + lane * 2];
        float hx = fmaf(p.x, w0.x, fmaf(p.y, w1.x, fmaf(p.z, w2.x, fmaf(p.w, w3.x, xc.x))));
        float hy = fmaf(p.x, w0.y, fmaf(p.y, w1.y, fmaf(p.z, w2.y, fmaf(p.w, w3.y, xc.y))));
        ax = fmaxf(ax, hx);   // acc >= 0 so this == max(acc, relu(h))
        ay = fmaxf(ay, hy);
    }
    float2 outv = make_float2(ax, ay);
    *(float2*)&g_seg[(size_t)node * 64 + lane * 2] = outv;
}

// ---------------------------------------------------------------- out = relu(seg @ W2 + b2)
// 32 nodes x 128 cols per block, 256 threads: 2 nodes x 8 cols per thread.
__global__ void k_out(const float* __restrict__ W2, const float* __restrict__ b2,
                      float* __restrict__ out, int n) {
    __shared__ float ss[32][65];
    __shared__ float ws[64][128];
    int n0 = blockIdx.x * 32;
    for (int i = threadIdx.x; i < 64 * 128; i += 256) ws[i >> 7][i & 127] = W2[i];
    for (int i = threadIdx.x; i < 32 * 64; i += 256) {
        int r = i >> 6, c = i & 63;
        ss[r][c] = (n0 + r < n) ? g_seg[(size_t)(n0 + r) * 64 + c] : 0.f;
    }
    __syncthreads();
    int tx = threadIdx.x & 15, ty = threadIdx.x >> 4;
    float acc[2][8];
#pragma unroll
    for (int j = 0; j < 8; j++) {
        float b = b2[tx * 8 + j];
        acc[0][j] = b; acc[1][j] = b;
    }
#pragma unroll 16
    for (int d = 0; d < 64; d++) {
        float a0 = ss[ty * 2 + 0][d];
        float a1 = ss[ty * 2 + 1][d];
        float4 wA = *(const float4*)&ws[d][tx * 8];
        float4 wB = *(const float4*)&ws[d][tx * 8 + 4];
        acc[0][0] = fmaf(a0, wA.x, acc[0][0]); acc[1][0] = fmaf(a1, wA.x, acc[1][0]);
        acc[0][1] = fmaf(a0, wA.y, acc[0][1]); acc[1][1] = fmaf(a1, wA.y, acc[1][1]);
        acc[0][2] = fmaf(a0, wA.z, acc[0][2]); acc[1][2] = fmaf(a1, wA.z, acc[1][2]);
        acc[0][3] = fmaf(a0, wA.w, acc[0][3]); acc[1][3] = fmaf(a1, wA.w, acc[1][3]);
        acc[0][4] = fmaf(a0, wB.x, acc[0][4]); acc[1][4] = fmaf(a1, wB.x, acc[1][4]);
        acc[0][5] = fmaf(a0, wB.y, acc[0][5]); acc[1][5] = fmaf(a1, wB.y, acc[1][5]);
        acc[0][6] = fmaf(a0, wB.z, acc[0][6]); acc[1][6] = fmaf(a1, wB.z, acc[1][6]);
        acc[0][7] = fmaf(a0, wB.w, acc[0][7]); acc[1][7] = fmaf(a1, wB.w, acc[1][7]);
    }
#pragma unroll
    for (int i = 0; i < 2; i++) {
        int node = n0 + ty * 2 + i;
        if (node < n) {
            float4 v0 = make_float4(fmaxf(acc[i][0], 0.f), fmaxf(acc[i][1], 0.f),
                                    fmaxf(acc[i][2], 0.f), fmaxf(acc[i][3], 0.f));
            float4 v1 = make_float4(fmaxf(acc[i][4], 0.f), fmaxf(acc[i][5], 0.f),
                                    fmaxf(acc[i][6], 0.f), fmaxf(acc[i][7], 0.f));
            *(float4*)&out[(size_t)node * 128 + tx * 8] = v0;
            *(float4*)&out[(size_t)node * 128 + tx * 8 + 4] = v1;
        }
    }
}

// ---------------------------------------------------------------- launch
extern "C" void kernel_launch(void* const* d_in, const int* in_sizes, int n_in,
                              void* d_out, int out_size) {
    const float* x   = (const float*)d_in[0];
    const float* pos = (const float*)d_in[1];
    const float* nrm = (const float*)d_in[2];
    const int*   ei  = (const int*)d_in[3];
    // d_in[4] = batch (unused)
    const float* W1  = (const float*)d_in[5];
    const float* b1  = (const float*)d_in[6];
    const float* W2  = (const float*)d_in[7];
    const float* b2  = (const float*)d_in[8];
    float* out = (float*)d_out;

    int N = in_sizes[1] / 3;
    int E = in_sizes[3] / 2;

    k_zero<<<(N + 255) / 256, 256>>>(N);
    k_xw<<<(N + 63) / 64, 256>>>(x, W1, b1, N);
    k_prep<<<(E + 255) / 256, 256>>>(ei, pos, E);
    k_scan<<<1, 1024>>>(N, E);
    k_scatter<<<(E + 255) / 256, 256>>>(ei, pos, nrm, E);
    k_node<<<(N * 32 + 255) / 256, 256>>>(W1, N);
    k_out<<<(N + 31) / 32, 256>>>(W2, b2, out, N);
}

// round 2
// speedup vs baseline: 1.6122x; 1.6122x over previous
#include <cuda_runtime.h>
#include <math.h>

#define NN 100000
#define EE 1600000

// Scratch (device globals; no allocation allowed)
__device__ float  g_xw[(size_t)NN * 64];    // x@W1[:64] + b1
__device__ float  g_seg[(size_t)NN * 64];   // segment-max result
__device__ float4 g_ppf[EE];                // CSR-ordered ppf features
__device__ int    g_col[EE];                // CSR-ordered target nodes
__device__ int    g_deg[NN];
__device__ int    g_off[NN + 1];
__device__ int    g_cur[NN];
__device__ int    g_bsum[128];              // per-1024-chunk block sums
__device__ double g_sum;
__device__ float  g_invmean;

// ---------------------------------------------------------------- zero
__global__ void k_zero(int n) {
    int i = blockIdx.x * 256 + threadIdx.x;
    if (i < n) g_deg[i] = 0;
    if (i == 0) g_sum = 0.0;
}

// ---------------------------------------------------------------- xw = x @ W1[:64,:] + b1
// 64 nodes x 64 cols per block, 256 threads, 4x4 register tile per thread.
__global__ void k_xw(const float* __restrict__ x, const float* __restrict__ W1,
                     const float* __restrict__ b1, int n) {
    __shared__ float xs[64][65];
    __shared__ float ws[64][64];
    int n0 = blockIdx.x * 64;
    for (int i = threadIdx.x; i < 4096; i += 256) ws[i >> 6][i & 63] = W1[i];
    for (int i = threadIdx.x; i < 4096; i += 256) {
        int r = i >> 6, c = i & 63;
        xs[r][c] = (n0 + r < n) ? x[(size_t)(n0 + r) * 64 + c] : 0.f;
    }
    __syncthreads();
    int tx = threadIdx.x & 15, ty = threadIdx.x >> 4;
    float acc[4][4];
#pragma unroll
    for (int j = 0; j < 4; j++) {
        float b = b1[tx * 4 + j];
#pragma unroll
        for (int i = 0; i < 4; i++) acc[i][j] = b;
    }
#pragma unroll 16
    for (int d = 0; d < 64; d++) {
        float a[4];
#pragma unroll
        for (int i = 0; i < 4; i++) a[i] = xs[ty * 4 + i][d];
        float4 w = *(const float4*)&ws[d][tx * 4];
#pragma unroll
        for (int i = 0; i < 4; i++) {
            acc[i][0] = fmaf(a[i], w.x, acc[i][0]);
            acc[i][1] = fmaf(a[i], w.y, acc[i][1]);
            acc[i][2] = fmaf(a[i], w.z, acc[i][2]);
            acc[i][3] = fmaf(a[i], w.w, acc[i][3]);
        }
    }
#pragma unroll
    for (int i = 0; i < 4; i++) {
        int node = n0 + ty * 4 + i;
        if (node < n) {
            float4 v = make_float4(acc[i][0], acc[i][1], acc[i][2], acc[i][3]);
            *(float4*)&g_xw[(size_t)node * 64 + tx * 4] = v;
        }
    }
}

// ---------------------------------------------------------------- per-edge: degree counts + sq-dist sum
// Block-level reduction of the dist sum: ONE double atomic per block (6250 total)
// instead of one per warp on a single contended address.
__global__ void k_prep(const int* __restrict__ ei, const float* __restrict__ pos, int E) {
    int e = blockIdx.x * 256 + threadIdx.x;
    float dist = 0.f;
    if (e < E) {
        int r = ei[e], c = ei[E + e];
        float dx = pos[c * 3 + 0] - pos[r * 3 + 0];
        float dy = pos[c * 3 + 1] - pos[r * 3 + 1];
        float dz = pos[c * 3 + 2] - pos[r * 3 + 2];
        dist = dx * dx + dy * dy + dz * dz;
        atomicAdd(&g_deg[r], 1);
    }
#pragma unroll
    for (int o = 16; o > 0; o >>= 1) dist += __shfl_down_sync(0xffffffffu, dist, o);
    __shared__ float wpart[8];
    int lane = threadIdx.x & 31, wid = threadIdx.x >> 5;
    if (lane == 0) wpart[wid] = dist;
    __syncthreads();
    if (threadIdx.x == 0) {
        float s = 0.f;
#pragma unroll
        for (int i = 0; i < 8; i++) s += wpart[i];
        atomicAdd(&g_sum, (double)s);
    }
}

// ---------------------------------------------------------------- multi-block exclusive scan
// Stage 1: each block scans 1024 degrees (4/thread), writes local-exclusive
// prefixes to g_off and its block total to g_bsum.
__global__ void k_scan1(int n) {
    int base = blockIdx.x * 1024 + threadIdx.x * 4;
    int d0 = 0, d1 = 0, d2 = 0, d3 = 0;
    if (base + 3 < n) {
        int4 v = *(const int4*)&g_deg[base];
        d0 = v.x; d1 = v.y; d2 = v.z; d3 = v.w;
    } else {
        if (base + 0 < n) d0 = g_deg[base + 0];
        if (base + 1 < n) d1 = g_deg[base + 1];
        if (base + 2 < n) d2 = g_deg[base + 2];
        if (base + 3 < n) d3 = g_deg[base + 3];
    }
    int s = d0 + d1 + d2 + d3;
    int lane = threadIdx.x & 31, wid = threadIdx.x >> 5;
    int v = s;
#pragma unroll
    for (int o = 1; o < 32; o <<= 1) {
        int y = __shfl_up_sync(0xffffffffu, v, o);
        if (lane >= o) v += y;
    }
    __shared__ int ws[8];
    if (lane == 31) ws[wid] = v;
    __syncthreads();
    if (threadIdx.x == 0) {
        int run = 0;
#pragma unroll
        for (int i = 0; i < 8; i++) { int t = ws[i]; ws[i] = run; run += t; }
        g_bsum[blockIdx.x] = run;
    }
    __syncthreads();
    int excl = v - s + ws[wid];
    if (base + 0 < n) g_off[base + 0] = excl;
    if (base + 1 < n) g_off[base + 1] = excl + d0;
    if (base + 2 < n) g_off[base + 2] = excl + d0 + d1;
    if (base + 3 < n) g_off[base + 3] = excl + d0 + d1 + d2;
}

// Stage 2: single small block scans the (<=128) block sums in-place (exclusive).
// Also finalizes g_off[n] = E and the inv-mean normalizer.
__global__ void k_scan2(int nb, int n, int E) {
    int t = threadIdx.x;  // blockDim = 128
    int s = (t < nb) ? g_bsum[t] : 0;
    int lane = t & 31, wid = t >> 5;
    int v = s;
#pragma unroll
    for (int o = 1; o < 32; o <<= 1) {
        int y = __shfl_up_sync(0xffffffffu, v, o);
        if (lane >= o) v += y;
    }
    __shared__ int ws[4];
    if (lane == 31) ws[wid] = v;
    __syncthreads();
    if (t == 0) {
        int run = 0;
#pragma unroll
        for (int i = 0; i < 4; i++) { int x = ws[i]; ws[i] = run; run += x; }
    }
    __syncthreads();
    int excl = v - s + ws[wid];
    if (t < nb) g_bsum[t] = excl;
    if (t == 0) {
        g_off[n] = E;
        g_invmean = (float)((double)(E + n) / g_sum);
    }
}

// Stage 3: add block offsets; init g_cur.
__global__ void k_scan3(int n) {
    int i = blockIdx.x * 256 + threadIdx.x;
    if (i >= n) return;
    int o = g_off[i] + g_bsum[i >> 10];
    g_off[i] = o;
    g_cur[i] = o;
}

// ---------------------------------------------------------------- ppf + scatter into CSR
__device__ __forceinline__ float ppf_angle(float ax, float ay, float az,
                                           float bx, float by, float bz) {
    float cx = ay * bz - az * by;
    float cy = az * bx - ax * bz;
    float cz = ax * by - ay * bx;
    float dot = ax * bx + ay * by + az * bz;
    return atan2f(sqrtf(cx * cx + cy * cy + cz * cz), dot);
}

__global__ void k_scatter(const int* __restrict__ ei, const float* __restrict__ pos,
                          const float* __restrict__ nrm, int E) {
    int e = blockIdx.x * 256 + threadIdx.x;
    if (e >= E) return;
    int r = ei[e], c = ei[E + e];
    float dx = pos[c * 3 + 0] - pos[r * 3 + 0];
    float dy = pos[c * 3 + 1] - pos[r * 3 + 1];
    float dz = pos[c * 3 + 2] - pos[r * 3 + 2];
    float n1x = nrm[r * 3 + 0], n1y = nrm[r * 3 + 1], n1z = nrm[r * 3 + 2];
    float n2x = nrm[c * 3 + 0], n2y = nrm[c * 3 + 1], n2z = nrm[c * 3 + 2];
    float dist = (dx * dx + dy * dy + dz * dz) * g_invmean;
    float a1 = ppf_angle(n1x, n1y, n1z, dx, dy, dz);
    float a2 = ppf_angle(n2x, n2y, n2z, dx, dy, dz);
    float a3 = ppf_angle(n1x, n1y, n1z, n2x, n2y, n2z);
    int p = atomicAdd(&g_cur[r], 1);
    g_col[p] = c;
    g_ppf[p] = make_float4(dist, a1, a2, a3);
}

// ---------------------------------------------------------------- warp-per-node max reduction
// lane owns dims [2*lane, 2*lane+1]; acc init = relu(xw[node]) handles the self-loop.
// Edge loop unrolled x2 so two independent g_xw gathers are in flight.
__global__ void k_node(const float* __restrict__ W1, int n) {
    int warp = (blockIdx.x * 256 + threadIdx.x) >> 5;
    int lane = threadIdx.x & 31;
    if (warp >= n) return;
    int node = warp;

    const float* Wp = W1 + 64 * 64;
    float2 w0 = *(const float2*)&Wp[0 * 64 + lane * 2];
    float2 w1 = *(const float2*)&Wp[1 * 64 + lane * 2];
    float2 w2 = *(const float2*)&Wp[2 * 64 + lane * 2];
    float2 w3 = *(const float2*)&Wp[3 * 64 + lane * 2];

    float2 xw = *(const float2*)&g_xw[(size_t)node * 64 + lane * 2];
    float ax = fmaxf(xw.x, 0.f);
    float ay = fmaxf(xw.y, 0.f);

    int beg = g_off[node];
    int end = g_off[node + 1];
    int i = beg;
    for (; i + 1 < end; i += 2) {
        int c0 = g_col[i];
        int c1 = g_col[i + 1];
        float4 p0 = g_ppf[i];
        float4 p1 = g_ppf[i + 1];
        float2 xc0 = *(const float2*)&g_xw[(size_t)c0 * 64 + lane * 2];
        float2 xc1 = *(const float2*)&g_xw[(size_t)c1 * 64 + lane * 2];
        float hx0 = fmaf(p0.x, w0.x, fmaf(p0.y, w1.x, fmaf(p0.z, w2.x, fmaf(p0.w, w3.x, xc0.x))));
        float hy0 = fmaf(p0.x, w0.y, fmaf(p0.y, w1.y, fmaf(p0.z, w2.y, fmaf(p0.w, w3.y, xc0.y))));
        float hx1 = fmaf(p1.x, w0.x, fmaf(p1.y, w1.x, fmaf(p1.z, w2.x, fmaf(p1.w, w3.x, xc1.x))));
        float hy1 = fmaf(p1.x, w0.y, fmaf(p1.y, w1.y, fmaf(p1.z, w2.y, fmaf(p1.w, w3.y, xc1.y))));
        ax = fmaxf(ax, fmaxf(hx0, hx1));
        ay = fmaxf(ay, fmaxf(hy0, hy1));
    }
    if (i < end) {
        int c = g_col[i];
        float4 p = g_ppf[i];
        float2 xc = *(const float2*)&g_xw[(size_t)c * 64 + lane * 2];
        float hx = fmaf(p.x, w0.x, fmaf(p.y, w1.x, fmaf(p.z, w2.x, fmaf(p.w, w3.x, xc.x))));
        float hy = fmaf(p.x, w0.y, fmaf(p.y, w1.y, fmaf(p.z, w2.y, fmaf(p.w, w3.y, xc.y))));
        ax = fmaxf(ax, hx);
        ay = fmaxf(ay, hy);
    }
    float2 outv = make_float2(ax, ay);
    *(float2*)&g_seg[(size_t)node * 64 + lane * 2] = outv;
}

// ---------------------------------------------------------------- out = relu(seg @ W2 + b2)
// 32 nodes x 128 cols per block, 256 threads: 2 nodes x 8 cols per thread.
__global__ void k_out(const float* __restrict__ W2, const float* __restrict__ b2,
                      float* __restrict__ out, int n) {
    __shared__ float ss[32][65];
    __shared__ float ws[64][128];
    int n0 = blockIdx.x * 32;
    for (int i = threadIdx.x; i < 64 * 128; i += 256) ws[i >> 7][i & 127] = W2[i];
    for (int i = threadIdx.x; i < 32 * 64; i += 256) {
        int r = i >> 6, c = i & 63;
        ss[r][c] = (n0 + r < n) ? g_seg[(size_t)(n0 + r) * 64 + c] : 0.f;
    }
    __syncthreads();
    int tx = threadIdx.x & 15, ty = threadIdx.x >> 4;
    float acc[2][8];
#pragma unroll
    for (int j = 0; j < 8; j++) {
        float b = b2[tx * 8 + j];
        acc[0][j] = b; acc[1][j] = b;
    }
#pragma unroll 16
    for (int d = 0; d < 64; d++) {
        float a0 = ss[ty * 2 + 0][d];
        float a1 = ss[ty * 2 + 1][d];
        float4 wA = *(const float4*)&ws[d][tx * 8];
        float4 wB = *(const float4*)&ws[d][tx * 8 + 4];
        acc[0][0] = fmaf(a0, wA.x, acc[0][0]); acc[1][0] = fmaf(a1, wA.x, acc[1][0]);
        acc[0][1] = fmaf(a0, wA.y, acc[0][1]); acc[1][1] = fmaf(a1, wA.y, acc[1][1]);
        acc[0][2] = fmaf(a0, wA.z, acc[0][2]); acc[1][2] = fmaf(a1, wA.z, acc[1][2]);
        acc[0][3] = fmaf(a0, wA.w, acc[0][3]); acc[1][3] = fmaf(a1, wA.w, acc[1][3]);
        acc[0][4] = fmaf(a0, wB.x, acc[0][4]); acc[1][4] = fmaf(a1, wB.x, acc[1][4]);
        acc[0][5] = fmaf(a0, wB.y, acc[0][5]); acc[1][5] = fmaf(a1, wB.y, acc[1][5]);
        acc[0][6] = fmaf(a0, wB.z, acc[0][6]); acc[1][6] = fmaf(a1, wB.z, acc[1][6]);
        acc[0][7] = fmaf(a0, wB.w, acc[0][7]); acc[1][7] = fmaf(a1, wB.w, acc[1][7]);
    }
#pragma unroll
    for (int i = 0; i < 2; i++) {
        int node = n0 + ty * 2 + i;
        if (node < n) {
            float4 v0 = make_float4(fmaxf(acc[i][0], 0.f), fmaxf(acc[i][1], 0.f),
                                    fmaxf(acc[i][2], 0.f), fmaxf(acc[i][3], 0.f));
            float4 v1 = make_float4(fmaxf(acc[i][4], 0.f), fmaxf(acc[i][5], 0.f),
                                    fmaxf(acc[i][6], 0.f), fmaxf(acc[i][7], 0.f));
            *(float4*)&out[(size_t)node * 128 + tx * 8] = v0;
            *(float4*)&out[(size_t)node * 128 + tx * 8 + 4] = v1;
        }
    }
}

// ---------------------------------------------------------------- launch
extern "C" void kernel_launch(void* const* d_in, const int* in_sizes, int n_in,
                              void* d_out, int out_size) {
    const float* x   = (const float*)d_in[0];
    const float* pos = (const float*)d_in[1];
    const float* nrm = (const float*)d_in[2];
    const int*   ei  = (const int*)d_in[3];
    // d_in[4] = batch (unused)
    const float* W1  = (const float*)d_in[5];
    const float* b1  = (const float*)d_in[6];
    const float* W2  = (const float*)d_in[7];
    const float* b2  = (const float*)d_in[8];
    float* out = (float*)d_out;

    int N = in_sizes[1] / 3;
    int E = in_sizes[3] / 2;
    int nb = (N + 1023) / 1024;

    k_zero<<<(N + 255) / 256, 256>>>(N);
    k_xw<<<(N + 63) / 64, 256>>>(x, W1, b1, N);
    k_prep<<<(E + 255) / 256, 256>>>(ei, pos, E);
    k_scan1<<<nb, 256>>>(N);
    k_scan2<<<1, 128>>>(nb, N, E);
    k_scan3<<<(N + 255) / 256, 256>>>(N);
    k_scatter<<<(E + 255) / 256, 256>>>(ei, pos, nrm, E);
    k_node<<<(N * 32 + 255) / 256, 256>>>(W1, N);
    k_out<<<(N + 31) / 32, 256>>>(W2, b2, out, N);
}